// round 12
// baseline (speedup 1.0000x reference)
#include <cuda_runtime.h>
#include <cuda_bf16.h>

// NeRF raw2outputs — R12: R11 (one warp/ray, 12 front-batched __ldcs loads,
// interleaved warp product-scans, tanh.approx sigmoid, __stwt weights) made
// PERSISTENT: grid = 740 blocks (148 SMs x 5 resident) grid-striding over
// rays, eliminating ~10 wave transitions + ragged tail of the 8192-block
// launch. Inner body identical to the 45.6us R11 kernel.
//
// Output layout (tuple flattened in order), N = num rays:
//   [0 , 3N)     rgb_map   [N,3]
//   [3N, 4N)     disp_map  [N,1]
//   [4N, 5N)     acc_map   [N,1]
//   [5N, 197N)   weights   [N,192]
//   [197N, 198N) depth_map [N,1]

#define FULL 0xffffffffu
#define NSAMP 192
#define NCHUNK 6
#define INF_DIST 1e10f
#define NBLOCKS 740          // 148 SMs x 5 blocks (48-reg residency limit)
#define WARPS_PER_BLK 8

__device__ __forceinline__ float fast_sigmoid(float x) {
    float t;
    asm("tanh.approx.f32 %0, %1;" : "=f"(t) : "f"(0.5f * x));
    return fmaf(0.5f, t, 0.5f);
}

__global__ __launch_bounds__(256)
void nerf_render_kernel(const float4* __restrict__ raw4,
                        const float*  __restrict__ z_vals,
                        const float*  __restrict__ rays_d,
                        float* __restrict__ out,
                        int N)
{
    const int warp_in_blk = threadIdx.x >> 5;
    const int lane        = threadIdx.x & 31;
    const int nwarps      = gridDim.x * WARPS_PER_BLK;

    float* __restrict__ wout = out + (long)5 * N;

    for (int ray = blockIdx.x * WARPS_PER_BLK + warp_in_blk; ray < N; ray += nwarps) {
        const long base = (long)ray * NSAMP;

        // ---- front-batch ALL global loads (12 independent LDGs in flight) ----
        float4 rv[NCHUNK];
        float  zv[NCHUNK];
#pragma unroll
        for (int c = 0; c < NCHUNK; ++c)
            rv[c] = __ldcs(&raw4[base + c * 32 + lane]);     // read-once stream
#pragma unroll
        for (int c = 0; c < NCHUNK; ++c)
            zv[c] = __ldcs(&z_vals[base + c * 32 + lane]);   // read-once stream

        const float dx = rays_d[3 * ray + 0];
        const float dy = rays_d[3 * ray + 1];
        const float dz = rays_d[3 * ray + 2];
        const float nrm = sqrtf(dx * dx + dy * dy + dz * dz);

        // ---- per-sample alpha and t = 1-alpha+eps ----
        float alpha[NCHUNK], p[NCHUNK];
#pragma unroll
        for (int c = 0; c < NCHUNK; ++c) {
            const float z  = zv[c];
            const float zn = __shfl_down_sync(FULL, z, 1);
            float dist;
            if (c < NCHUNK - 1) {
                const float zfn = __shfl_sync(FULL, zv[c + 1], 0);
                dist = (lane == 31) ? (zfn - z) : (zn - z);
            } else {
                dist = (lane == 31) ? INF_DIST : (zn - z);
            }
            dist *= nrm;
            const float sigma = fmaxf(rv[c].w, 0.f);
            alpha[c] = 1.f - __expf(-sigma * dist);
            p[c] = 1.f - alpha[c] + 1e-10f;
        }

        // ---- 6 interleaved inclusive product scans ----
#pragma unroll
        for (int off = 1; off < 32; off <<= 1) {
#pragma unroll
            for (int c = 0; c < NCHUNK; ++c) {
                const float u = __shfl_up_sync(FULL, p[c], off);
                if (lane >= off) p[c] *= u;
            }
        }

        // exclusive prefix within chunk + chunk totals
        float exc[NCHUNK], tot[NCHUNK];
#pragma unroll
        for (int c = 0; c < NCHUNK; ++c) {
            exc[c] = __shfl_up_sync(FULL, p[c], 1);
            if (lane == 0) exc[c] = 1.f;
            tot[c] = __shfl_sync(FULL, p[c], 31);
        }

        // cross-chunk carry prefix
        float carry[NCHUNK];
        carry[0] = 1.f;
#pragma unroll
        for (int c = 1; c < NCHUNK; ++c)
            carry[c] = carry[c - 1] * tot[c - 1];

        // ---- weights, accumulation, write-through stores ----
        float r_sum = 0.f, g_sum = 0.f, b_sum = 0.f, d_sum = 0.f, a_sum = 0.f;

#pragma unroll
        for (int c = 0; c < NCHUNK; ++c) {
            const float w = alpha[c] * carry[c] * exc[c];

            const float sr = fast_sigmoid(rv[c].x);
            const float sg = fast_sigmoid(rv[c].y);
            const float sb = fast_sigmoid(rv[c].z);

            r_sum += w * sr;
            g_sum += w * sg;
            b_sum += w * sb;
            d_sum += w * zv[c];
            a_sum += w;

            __stwt(&wout[base + c * 32 + lane], w);
        }

        // ---- warp reductions ----
#pragma unroll
        for (int off = 16; off; off >>= 1) {
            r_sum += __shfl_down_sync(FULL, r_sum, off);
            g_sum += __shfl_down_sync(FULL, g_sum, off);
            b_sum += __shfl_down_sync(FULL, b_sum, off);
            d_sum += __shfl_down_sync(FULL, d_sum, off);
            a_sum += __shfl_down_sync(FULL, a_sum, off);
        }

        if (lane == 0) {
            out[3 * ray + 0] = r_sum;
            out[3 * ray + 1] = g_sum;
            out[3 * ray + 2] = b_sum;

            const float acc = a_sum;
            float depth = d_sum;
            if (acc <= 1e-10f) depth = INF_DIST;
            const float ratio = __fdividef(depth, acc);
            const float disp  = __fdividef(1.f, fmaxf(1e-10f, ratio));

            out[(long)3 * N + ray]   = disp;
            out[(long)4 * N + ray]   = acc;
            out[(long)197 * N + ray] = depth;
        }
    }
}

extern "C" void kernel_launch(void* const* d_in, const int* in_sizes, int n_in,
                              void* d_out, int out_size)
{
    const float4* raw4   = (const float4*)d_in[0];
    const float*  z_vals = (const float*)d_in[1];
    const float*  rays_d = (const float*)d_in[2];
    float* out = (float*)d_out;

    const int N = in_sizes[2] / 3;          // num rays from rays_d
    nerf_render_kernel<<<NBLOCKS, WARPS_PER_BLK * 32>>>(raw4, z_vals, rays_d, out, N);
}

// round 13
// speedup vs baseline: 1.2252x; 1.2252x over previous
#include <cuda_runtime.h>
#include <cuda_bf16.h>

// NeRF raw2outputs — FINAL = R11 (best measured: 45.6us, kernel 41.8us,
// 6.2TB/s on a ~290MB minimum-traffic stream).
//
// Structure: one warp per ray, 6 chunks of 32 samples.
//  - All 12 global loads front-batched with __ldcs (per-warp MLP is the
//    binding resource; regs=48/occ~53% is the empirically optimal trade —
//    every occupancy-raising or staging variant regressed DRAM throughput).
//  - 6 interleaved warp product-scans + cross-chunk carry prefix for the
//    exclusive transmittance cumprod (no serial chain).
//  - Single-MUFU tanh.approx sigmoid.
//  - __stwt on the 52MB write-once weights stream (R11: -2us vs __stcs, by
//    removing L2 dirty residency from the store path).
//  - One-shot 8192-block launch (persistent grid-stride regressed: wrapper
//    pushed regs to 64 and broke the load batch).
//
// Output layout (tuple flattened in order), N = num rays:
//   [0 , 3N)     rgb_map   [N,3]
//   [3N, 4N)     disp_map  [N,1]
//   [4N, 5N)     acc_map   [N,1]
//   [5N, 197N)   weights   [N,192]
//   [197N, 198N) depth_map [N,1]

#define FULL 0xffffffffu
#define NSAMP 192
#define NCHUNK 6
#define INF_DIST 1e10f

__device__ __forceinline__ float fast_sigmoid(float x) {
    float t;
    asm("tanh.approx.f32 %0, %1;" : "=f"(t) : "f"(0.5f * x));
    return fmaf(0.5f, t, 0.5f);
}

__global__ __launch_bounds__(256)
void nerf_render_kernel(const float4* __restrict__ raw4,
                        const float*  __restrict__ z_vals,
                        const float*  __restrict__ rays_d,
                        float* __restrict__ out,
                        int N)
{
    const int warp_in_blk = threadIdx.x >> 5;
    const int lane        = threadIdx.x & 31;
    const int ray = blockIdx.x * (blockDim.x >> 5) + warp_in_blk;
    if (ray >= N) return;

    const long base = (long)ray * NSAMP;

    // ---- front-batch ALL global loads (12 independent LDGs in flight) ----
    float4 rv[NCHUNK];
    float  zv[NCHUNK];
#pragma unroll
    for (int c = 0; c < NCHUNK; ++c)
        rv[c] = __ldcs(&raw4[base + c * 32 + lane]);     // read-once stream
#pragma unroll
    for (int c = 0; c < NCHUNK; ++c)
        zv[c] = __ldcs(&z_vals[base + c * 32 + lane]);   // read-once stream

    const float dx = rays_d[3 * ray + 0];
    const float dy = rays_d[3 * ray + 1];
    const float dz = rays_d[3 * ray + 2];
    const float nrm = sqrtf(dx * dx + dy * dy + dz * dz);

    // ---- per-sample alpha and t = 1-alpha+eps (independent across chunks) ----
    float alpha[NCHUNK], p[NCHUNK];
#pragma unroll
    for (int c = 0; c < NCHUNK; ++c) {
        const float z  = zv[c];
        const float zn = __shfl_down_sync(FULL, z, 1);
        float dist;
        if (c < NCHUNK - 1) {
            const float zfn = __shfl_sync(FULL, zv[c + 1], 0);
            dist = (lane == 31) ? (zfn - z) : (zn - z);
        } else {
            dist = (lane == 31) ? INF_DIST : (zn - z);
        }
        dist *= nrm;
        const float sigma = fmaxf(rv[c].w, 0.f);
        alpha[c] = 1.f - __expf(-sigma * dist);
        p[c] = 1.f - alpha[c] + 1e-10f;
    }

    // ---- 6 independent inclusive product scans, interleaved for ILP ----
#pragma unroll
    for (int off = 1; off < 32; off <<= 1) {
#pragma unroll
        for (int c = 0; c < NCHUNK; ++c) {
            const float u = __shfl_up_sync(FULL, p[c], off);
            if (lane >= off) p[c] *= u;
        }
    }

    // exclusive prefix within chunk + chunk totals
    float exc[NCHUNK], tot[NCHUNK];
#pragma unroll
    for (int c = 0; c < NCHUNK; ++c) {
        exc[c] = __shfl_up_sync(FULL, p[c], 1);
        if (lane == 0) exc[c] = 1.f;
        tot[c] = __shfl_sync(FULL, p[c], 31);
    }

    // cross-chunk carry prefix
    float carry[NCHUNK];
    carry[0] = 1.f;
#pragma unroll
    for (int c = 1; c < NCHUNK; ++c)
        carry[c] = carry[c - 1] * tot[c - 1];

    // ---- weights, color/depth accumulation, write-through stores ----
    float* __restrict__ wout = out + (long)5 * N;
    float r_sum = 0.f, g_sum = 0.f, b_sum = 0.f, d_sum = 0.f, a_sum = 0.f;

#pragma unroll
    for (int c = 0; c < NCHUNK; ++c) {
        const float w = alpha[c] * carry[c] * exc[c];

        const float sr = fast_sigmoid(rv[c].x);
        const float sg = fast_sigmoid(rv[c].y);
        const float sb = fast_sigmoid(rv[c].z);

        r_sum += w * sr;
        g_sum += w * sg;
        b_sum += w * sb;
        d_sum += w * zv[c];
        a_sum += w;

        __stwt(&wout[base + c * 32 + lane], w);   // write-through: no L2 dirty residency
    }

    // ---- warp reductions ----
#pragma unroll
    for (int off = 16; off; off >>= 1) {
        r_sum += __shfl_down_sync(FULL, r_sum, off);
        g_sum += __shfl_down_sync(FULL, g_sum, off);
        b_sum += __shfl_down_sync(FULL, b_sum, off);
        d_sum += __shfl_down_sync(FULL, d_sum, off);
        a_sum += __shfl_down_sync(FULL, a_sum, off);
    }

    if (lane == 0) {
        out[3 * ray + 0] = r_sum;
        out[3 * ray + 1] = g_sum;
        out[3 * ray + 2] = b_sum;

        const float acc = a_sum;
        float depth = d_sum;
        if (acc <= 1e-10f) depth = INF_DIST;
        const float ratio = __fdividef(depth, acc);
        const float disp  = __fdividef(1.f, fmaxf(1e-10f, ratio));

        out[(long)3 * N + ray]   = disp;
        out[(long)4 * N + ray]   = acc;
        out[(long)197 * N + ray] = depth;
    }
}

extern "C" void kernel_launch(void* const* d_in, const int* in_sizes, int n_in,
                              void* d_out, int out_size)
{
    const float4* raw4   = (const float4*)d_in[0];
    const float*  z_vals = (const float*)d_in[1];
    const float*  rays_d = (const float*)d_in[2];
    float* out = (float*)d_out;

    const int N = in_sizes[2] / 3;          // num rays from rays_d
    const int warps_per_blk = 8;            // 256 threads
    const int blocks = (N + warps_per_blk - 1) / warps_per_blk;
    nerf_render_kernel<<<blocks, warps_per_blk * 32>>>(raw4, z_vals, rays_d, out, N);
}

// round 14
// speedup vs baseline: 1.2691x; 1.0358x over previous
#include <cuda_runtime.h>
#include <cuda_bf16.h>

// NeRF raw2outputs — R14: R11 body (one warp/ray, 12 front-batched __ldcs
// loads, interleaved product scans, tanh.approx sigmoid, __stwt weights)
// with 128-thread CTAs (4 warps) instead of 256: halves the CTA allocation
// granule so finished warp-quads are backfilled sooner. Per-warp SASS body
// unchanged. R11/R13 identical-source runs bound bench noise at ~±1.5us.
//
// Output layout (tuple flattened in order), N = num rays:
//   [0 , 3N)     rgb_map   [N,3]
//   [3N, 4N)     disp_map  [N,1]
//   [4N, 5N)     acc_map   [N,1]
//   [5N, 197N)   weights   [N,192]
//   [197N, 198N) depth_map [N,1]

#define FULL 0xffffffffu
#define NSAMP 192
#define NCHUNK 6
#define INF_DIST 1e10f
#define BLKDIM 128

__device__ __forceinline__ float fast_sigmoid(float x) {
    float t;
    asm("tanh.approx.f32 %0, %1;" : "=f"(t) : "f"(0.5f * x));
    return fmaf(0.5f, t, 0.5f);
}

__global__ __launch_bounds__(BLKDIM)
void nerf_render_kernel(const float4* __restrict__ raw4,
                        const float*  __restrict__ z_vals,
                        const float*  __restrict__ rays_d,
                        float* __restrict__ out,
                        int N)
{
    const int warp_in_blk = threadIdx.x >> 5;
    const int lane        = threadIdx.x & 31;
    const int ray = blockIdx.x * (BLKDIM >> 5) + warp_in_blk;
    if (ray >= N) return;

    const long base = (long)ray * NSAMP;

    // ---- front-batch ALL global loads (12 independent LDGs in flight) ----
    float4 rv[NCHUNK];
    float  zv[NCHUNK];
#pragma unroll
    for (int c = 0; c < NCHUNK; ++c)
        rv[c] = __ldcs(&raw4[base + c * 32 + lane]);     // read-once stream
#pragma unroll
    for (int c = 0; c < NCHUNK; ++c)
        zv[c] = __ldcs(&z_vals[base + c * 32 + lane]);   // read-once stream

    const float dx = rays_d[3 * ray + 0];
    const float dy = rays_d[3 * ray + 1];
    const float dz = rays_d[3 * ray + 2];
    const float nrm = sqrtf(dx * dx + dy * dy + dz * dz);

    // ---- per-sample alpha and t = 1-alpha+eps (independent across chunks) ----
    float alpha[NCHUNK], p[NCHUNK];
#pragma unroll
    for (int c = 0; c < NCHUNK; ++c) {
        const float z  = zv[c];
        const float zn = __shfl_down_sync(FULL, z, 1);
        float dist;
        if (c < NCHUNK - 1) {
            const float zfn = __shfl_sync(FULL, zv[c + 1], 0);
            dist = (lane == 31) ? (zfn - z) : (zn - z);
        } else {
            dist = (lane == 31) ? INF_DIST : (zn - z);
        }
        dist *= nrm;
        const float sigma = fmaxf(rv[c].w, 0.f);
        alpha[c] = 1.f - __expf(-sigma * dist);
        p[c] = 1.f - alpha[c] + 1e-10f;
    }

    // ---- 6 independent inclusive product scans, interleaved for ILP ----
#pragma unroll
    for (int off = 1; off < 32; off <<= 1) {
#pragma unroll
        for (int c = 0; c < NCHUNK; ++c) {
            const float u = __shfl_up_sync(FULL, p[c], off);
            if (lane >= off) p[c] *= u;
        }
    }

    // exclusive prefix within chunk + chunk totals
    float exc[NCHUNK], tot[NCHUNK];
#pragma unroll
    for (int c = 0; c < NCHUNK; ++c) {
        exc[c] = __shfl_up_sync(FULL, p[c], 1);
        if (lane == 0) exc[c] = 1.f;
        tot[c] = __shfl_sync(FULL, p[c], 31);
    }

    // cross-chunk carry prefix
    float carry[NCHUNK];
    carry[0] = 1.f;
#pragma unroll
    for (int c = 1; c < NCHUNK; ++c)
        carry[c] = carry[c - 1] * tot[c - 1];

    // ---- weights, color/depth accumulation, write-through stores ----
    float* __restrict__ wout = out + (long)5 * N;
    float r_sum = 0.f, g_sum = 0.f, b_sum = 0.f, d_sum = 0.f, a_sum = 0.f;

#pragma unroll
    for (int c = 0; c < NCHUNK; ++c) {
        const float w = alpha[c] * carry[c] * exc[c];

        const float sr = fast_sigmoid(rv[c].x);
        const float sg = fast_sigmoid(rv[c].y);
        const float sb = fast_sigmoid(rv[c].z);

        r_sum += w * sr;
        g_sum += w * sg;
        b_sum += w * sb;
        d_sum += w * zv[c];
        a_sum += w;

        __stwt(&wout[base + c * 32 + lane], w);   // write-through stream
    }

    // ---- warp reductions ----
#pragma unroll
    for (int off = 16; off; off >>= 1) {
        r_sum += __shfl_down_sync(FULL, r_sum, off);
        g_sum += __shfl_down_sync(FULL, g_sum, off);
        b_sum += __shfl_down_sync(FULL, b_sum, off);
        d_sum += __shfl_down_sync(FULL, d_sum, off);
        a_sum += __shfl_down_sync(FULL, a_sum, off);
    }

    if (lane == 0) {
        out[3 * ray + 0] = r_sum;
        out[3 * ray + 1] = g_sum;
        out[3 * ray + 2] = b_sum;

        const float acc = a_sum;
        float depth = d_sum;
        if (acc <= 1e-10f) depth = INF_DIST;
        const float ratio = __fdividef(depth, acc);
        const float disp  = __fdividef(1.f, fmaxf(1e-10f, ratio));

        out[(long)3 * N + ray]   = disp;
        out[(long)4 * N + ray]   = acc;
        out[(long)197 * N + ray] = depth;
    }
}

extern "C" void kernel_launch(void* const* d_in, const int* in_sizes, int n_in,
                              void* d_out, int out_size)
{
    const float4* raw4   = (const float4*)d_in[0];
    const float*  z_vals = (const float*)d_in[1];
    const float*  rays_d = (const float*)d_in[2];
    float* out = (float*)d_out;

    const int N = in_sizes[2] / 3;          // num rays from rays_d
    const int warps_per_blk = BLKDIM / 32;  // 4
    const int blocks = (N + warps_per_blk - 1) / warps_per_blk;
    nerf_render_kernel<<<blocks, BLKDIM>>>(raw4, z_vals, rays_d, out, N);
}